// round 5
// baseline (speedup 1.0000x reference)
#include <cuda_runtime.h>

#define EPS 1e-8f
#define B_ 64
#define O_ 64
#define I_ 1152
#define D_ 16
#define NCH 9          // i-chunks in vote kernel (1152 = 9*128)
#define CHI 128
#define NSPLIT 2       // i-splits in e-step kernel (1152 = 2*576)
#define ISPLIT 576
#define TI 8           // i-tile inside e-step kernel
#define NTILE 72       // 576 / 8
#define INVT0 5.0e-4f          // 0.01*(1-0.95)
#define INVT1 9.75e-4f         // 0.01*(1-0.95^2)
#define TWO_PI 6.283185307179586f

// ---- scratch (device globals; no runtime allocation) ----
__device__ float g_V[B_ * O_ * I_ * D_];          // 302 MB vote buffer, layout (b,o,i,e)
__device__ float g_ai[B_ * I_];
__device__ float g_rsum0[B_];
__device__ float g_PA1[O_ * NCH * B_ * D_];       // iter-0 partial  sum w*V
__device__ float g_PA2[O_ * NCH * B_ * D_];       // iter-0 partial  sum w*V^2
__device__ float g_mean[B_ * O_ * D_];
__device__ float g_i2v[B_ * O_ * D_];             // 1/(2*var+EPS)
__device__ float g_coef[B_ * O_];                 // a_j/(p1+EPS)
__device__ float g_P1[NSPLIT * B_ * O_ * D_];     // iter-1 partial sum w*V
__device__ float g_P2[NSPLIT * B_ * O_ * D_];     // iter-1 partial sum w*V^2
__device__ float g_Pr[NSPLIT * B_ * O_];          // iter-1 partial sum w

// ---------------------------------------------------------------------------
// a_i[b,i] = ||u[b,i,:]+EPS||  and  rsum0[b] = (1/O) * sum_i a_i  (iter-0 rr_sum)
// ---------------------------------------------------------------------------
__global__ void k_ai(const float* __restrict__ u) {
    int b = blockIdx.x;
    int t = threadIdx.x;
    __shared__ float red[256];
    float local = 0.f;
    for (int i = t; i < I_; i += 256) {
        const float4* up = (const float4*)(u + (size_t)(b * I_ + i) * D_);
        float4 a0 = up[0], a1 = up[1], a2 = up[2], a3 = up[3];
        float s = 0.f;
        s += (a0.x+EPS)*(a0.x+EPS) + (a0.y+EPS)*(a0.y+EPS) + (a0.z+EPS)*(a0.z+EPS) + (a0.w+EPS)*(a0.w+EPS);
        s += (a1.x+EPS)*(a1.x+EPS) + (a1.y+EPS)*(a1.y+EPS) + (a1.z+EPS)*(a1.z+EPS) + (a1.w+EPS)*(a1.w+EPS);
        s += (a2.x+EPS)*(a2.x+EPS) + (a2.y+EPS)*(a2.y+EPS) + (a2.z+EPS)*(a2.z+EPS) + (a2.w+EPS)*(a2.w+EPS);
        s += (a3.x+EPS)*(a3.x+EPS) + (a3.y+EPS)*(a3.y+EPS) + (a3.z+EPS)*(a3.z+EPS) + (a3.w+EPS)*(a3.w+EPS);
        float av = sqrtf(s);
        g_ai[b * I_ + i] = av;
        local += av;
    }
    red[t] = local;
    __syncthreads();
    for (int st = 128; st > 0; st >>= 1) {
        if (t < st) red[t] += red[t + st];
        __syncthreads();
    }
    if (t == 0) g_rsum0[b] = red[0] * (1.f / O_);
}

// ---------------------------------------------------------------------------
// Votes V[b,o,i,e] = u[b,i,:]·W[o,i,e,:] + EPS + bias[o,e]
// fused with iter-0 m-step moment accumulation (rr uniform -> w = a_i/64).
// Grid (NCH, O); each block owns W[o, i-chunk] exclusively (W read once from HBM)
// and serves all 64 b's.  Thread: b = t>>2, eg = t&3 (4 output dims each).
// ---------------------------------------------------------------------------
__global__ void __launch_bounds__(256) k_votes(const float* __restrict__ u,
                                               const float* __restrict__ W,
                                               const float* __restrict__ bias) {
    int ic = blockIdx.x;
    int o  = blockIdx.y;
    int t  = threadIdx.x;
    int eg = t & 3;
    int b  = t >> 2;
    float4 bi = *(const float4*)(bias + o * D_ + eg * 4);
    float bv[4] = {bi.x, bi.y, bi.z, bi.w};
    float s1[4] = {0.f, 0.f, 0.f, 0.f};
    float s2[4] = {0.f, 0.f, 0.f, 0.f};
    int i0 = ic * CHI;
    for (int ii = 0; ii < CHI; ++ii) {
        int i = i0 + ii;
        const float4* up = (const float4*)(u + (size_t)(b * I_ + i) * D_);
        float4 u0 = up[0], u1 = up[1], u2 = up[2], u3 = up[3];
        const float4* wp = (const float4*)(W + (size_t)(o * I_ + i) * 256 + eg * 64);
        float v[4];
#pragma unroll
        for (int j = 0; j < 4; ++j) {
            float4 w0 = wp[j*4+0], w1 = wp[j*4+1], w2 = wp[j*4+2], w3 = wp[j*4+3];
            float acc = u0.x*w0.x + u0.y*w0.y + u0.z*w0.z + u0.w*w0.w
                      + u1.x*w1.x + u1.y*w1.y + u1.z*w1.z + u1.w*w1.w
                      + u2.x*w2.x + u2.y*w2.y + u2.z*w2.z + u2.w*w2.w
                      + u3.x*w3.x + u3.y*w3.y + u3.z*w3.z + u3.w*w3.w;
            v[j] = acc + EPS + bv[j];
        }
        float w = g_ai[b * I_ + i] * (1.f / O_);
        *(float4*)(g_V + (size_t)((b * O_ + o) * I_ + i) * D_ + eg * 4) =
            make_float4(v[0], v[1], v[2], v[3]);
#pragma unroll
        for (int j = 0; j < 4; ++j) {
            s1[j] += w * v[j];
            s2[j] += w * v[j] * v[j];
        }
    }
    int p = ((o * NCH + ic) * B_ + b) * D_ + eg * 4;
    *(float4*)(g_PA1 + p) = make_float4(s1[0], s1[1], s1[2], s1[3]);
    *(float4*)(g_PA2 + p) = make_float4(s2[0], s2[1], s2[2], s2[3]);
}

// ---------------------------------------------------------------------------
// Iter-0 m-step finalize: combine 9 chunk partials -> mean, 1/(2var+EPS),
// coef = a_j/(p1+EPS).  One 16-lane group per (b,o), lane = e.
// ---------------------------------------------------------------------------
__global__ void k_mstep0(const float* __restrict__ beta_a,
                         const float* __restrict__ beta_u) {
    int gp = blockIdx.x * blockDim.x + threadIdx.x;
    int pair = gp >> 4;
    if (pair >= B_ * O_) return;
    int e = gp & 15;
    int b = pair >> 6;
    int o = pair & 63;
    float S = g_rsum0[b];
    float d = S + EPS;
    float s1 = 0.f, s2 = 0.f;
#pragma unroll
    for (int ch = 0; ch < NCH; ++ch) {
        int p = ((o * NCH + ch) * B_ + b) * D_ + e;
        s1 += g_PA1[p];
        s2 += g_PA2[p];
    }
    float mm  = s1 / d;
    float var = (s2 - 2.f * mm * s1 + mm * mm * S) / d + 1e-4f;
    g_mean[pair * D_ + e] = mm;
    g_i2v[pair * D_ + e]  = 1.f / (2.f * var + EPS);
    float lsum = logf(var);
    float pr   = var;
#pragma unroll
    for (int off = 8; off > 0; off >>= 1) {
        lsum += __shfl_xor_sync(0xffffffffu, lsum, off, 16);
        pr   *= __shfl_xor_sync(0xffffffffu, pr,   off, 16);
    }
    if (e == 0) {
        float cost = S * (16.f * beta_u[o] + lsum);
        float aj = 1.f / (1.f + __expf(-(INVT0 * (beta_a[o] - cost))));
        float p1 = sqrtf(TWO_PI * pr + EPS);
        g_coef[pair] = aj / (p1 + EPS);
    }
}

// ---------------------------------------------------------------------------
// Fused e-step + iter-1 m-step moments.  Block = (split, b); 256 threads:
// o = t&63, eg = t>>6 (4 e's each).  Per 8-i tile:
//   stage1: each thread loads its V float4 (kept in regs), partial Mahalanobis
//   stage2: combine 4 eg-partials, ap = coef*exp(-la)
//   stage3: warp w normalizes row ti=w across o (softmax denom) and applies a_i
//   stage4: accumulate w*V, w*V^2, w using the register-resident V
// Deterministic partials per (split,b,o,e).
// ---------------------------------------------------------------------------
__global__ void __launch_bounds__(256) k_estep() {
    int s = blockIdx.x;
    int b = blockIdx.y;
    int t = threadIdx.x;
    __shared__ float sM[O_ * D_];
    __shared__ float sIV[O_ * D_];
    __shared__ float sCoef[O_];
    __shared__ float plbuf[TI][O_][5];    // pad 5 -> conflict-free (stride 5 coprime 32)
    __shared__ float apS[TI][O_ + 1];
    for (int k = t; k < O_ * D_; k += 256) {
        sM[k]  = g_mean[b * O_ * D_ + k];
        sIV[k] = g_i2v[b * O_ * D_ + k];
    }
    if (t < O_) sCoef[t] = g_coef[b * O_ + t];
    __syncthreads();
    int o  = t & 63;
    int eg = t >> 6;
    int w  = t >> 5;
    int lane = t & 31;
    float m0 = sM[o*D_ + eg*4 + 0], m1 = sM[o*D_ + eg*4 + 1];
    float m2 = sM[o*D_ + eg*4 + 2], m3 = sM[o*D_ + eg*4 + 3];
    float iv0 = sIV[o*D_ + eg*4 + 0], iv1 = sIV[o*D_ + eg*4 + 1];
    float iv2 = sIV[o*D_ + eg*4 + 2], iv3 = sIV[o*D_ + eg*4 + 3];
    float cf = sCoef[o];
    float a10 = 0.f, a11 = 0.f, a12 = 0.f, a13 = 0.f;
    float a20 = 0.f, a21 = 0.f, a22 = 0.f, a23 = 0.f;
    float rsum = 0.f;
    const float* Vb = g_V + (size_t)(b * O_ + o) * I_ * D_ + eg * 4;
    for (int tile = 0; tile < NTILE; ++tile) {
        int i0 = s * ISPLIT + tile * TI;
        float4 vv[TI];
#pragma unroll
        for (int ti = 0; ti < TI; ++ti) {
            vv[ti] = *(const float4*)(Vb + (size_t)(i0 + ti) * D_);
            float d0 = vv[ti].x - m0, d1 = vv[ti].y - m1;
            float d2 = vv[ti].z - m2, d3 = vv[ti].w - m3;
            plbuf[ti][o][eg] = d0*d0*iv0 + d1*d1*iv1 + d2*d2*iv2 + d3*d3*iv3;
        }
        __syncthreads();
#pragma unroll
        for (int q = 0; q < 2; ++q) {
            int ti = eg * 2 + q;
            float la = plbuf[ti][o][0] + plbuf[ti][o][1] + plbuf[ti][o][2] + plbuf[ti][o][3];
            apS[ti][o] = cf * __expf(-la);
        }
        __syncthreads();
        {
            float x = apS[w][lane] + apS[w][lane + 32];
#pragma unroll
            for (int off = 16; off > 0; off >>= 1)
                x += __shfl_xor_sync(0xffffffffu, x, off);
            float aiv = g_ai[b * I_ + i0 + w];
            float sc = aiv / (x + EPS);        // rr*a_i = ap/(sum+EPS) * a_i
            apS[w][lane]      *= sc;
            apS[w][lane + 32] *= sc;
        }
        __syncthreads();
#pragma unroll
        for (int ti = 0; ti < TI; ++ti) {
            float wv = apS[ti][o];
            a10 += wv * vv[ti].x; a11 += wv * vv[ti].y;
            a12 += wv * vv[ti].z; a13 += wv * vv[ti].w;
            a20 += wv * vv[ti].x * vv[ti].x; a21 += wv * vv[ti].y * vv[ti].y;
            a22 += wv * vv[ti].z * vv[ti].z; a23 += wv * vv[ti].w * vv[ti].w;
            if (eg == 0) rsum += wv;
        }
        __syncthreads();
    }
    int p = ((s * B_ + b) * O_ + o) * D_ + eg * 4;
    *(float4*)(g_P1 + p) = make_float4(a10, a11, a12, a13);
    *(float4*)(g_P2 + p) = make_float4(a20, a21, a22, a23);
    if (eg == 0) g_Pr[(s * B_ + b) * O_ + o] = rsum;
}

// ---------------------------------------------------------------------------
// Iter-1 m-step finalize + output:
// out[b,o,e] = a_j * mean / (||mean+EPS|| + EPS)
// ---------------------------------------------------------------------------
__global__ void k_final(const float* __restrict__ beta_a,
                        const float* __restrict__ beta_u,
                        float* __restrict__ out) {
    int gp = blockIdx.x * blockDim.x + threadIdx.x;
    int pair = gp >> 4;
    if (pair >= B_ * O_) return;
    int e = gp & 15;
    int o = pair & 63;
    float S = g_Pr[pair] + g_Pr[B_ * O_ + pair];
    float d = S + EPS;
    float s1 = g_P1[pair * D_ + e] + g_P1[B_ * O_ * D_ + pair * D_ + e];
    float s2 = g_P2[pair * D_ + e] + g_P2[B_ * O_ * D_ + pair * D_ + e];
    float mm  = s1 / d;
    float var = (s2 - 2.f * mm * s1 + mm * mm * S) / d + 1e-4f;
    float lsum = logf(var);
    float me = mm + EPS;
    float nr = me * me;
#pragma unroll
    for (int off = 8; off > 0; off >>= 1) {
        lsum += __shfl_xor_sync(0xffffffffu, lsum, off, 16);
        nr   += __shfl_xor_sync(0xffffffffu, nr,   off, 16);
    }
    float cost = S * (16.f * beta_u[o] + lsum);
    float aj = 1.f / (1.f + __expf(-(INVT1 * (beta_a[o] - cost))));
    out[pair * D_ + e] = aj * mm / (sqrtf(nr) + EPS);
}

extern "C" void kernel_launch(void* const* d_in, const int* in_sizes, int n_in,
                              void* d_out, int out_size) {
    const float* u      = (const float*)d_in[0];
    const float* W      = (const float*)d_in[1];
    const float* beta_a = (const float*)d_in[2];
    const float* beta_u = (const float*)d_in[3];
    const float* bias   = (const float*)d_in[4];
    float* out = (float*)d_out;

    k_ai<<<B_, 256>>>(u);
    k_votes<<<dim3(NCH, O_), 256>>>(u, W, bias);
    k_mstep0<<<(B_ * O_ * 16 + 255) / 256, 256>>>(beta_a, beta_u);
    k_estep<<<dim3(NSPLIT, B_), 256>>>();
    k_final<<<(B_ * O_ * 16 + 255) / 256, 256>>>(beta_a, beta_u, out);
}

// round 9
// speedup vs baseline: 1.8311x; 1.8311x over previous
#include <cuda_runtime.h>

#define EPS 1e-8f
#define B_ 64
#define O_ 64
#define I_ 1152
#define D_ 16
#define IC 16           // i-chunk per vote block
#define NCHV 72         // 1152/16 chunks
#define NSPLIT 24       // i-splits in e-step kernel (1152 = 24*48)
#define ISPLIT 48
#define TI 8            // i-tile inside e-step kernel
#define NTILE 6         // 48 / 8
#define INVT0 5.0e-4f          // 0.01*(1-0.95)
#define INVT1 9.75e-4f         // 0.01*(1-0.95^2)
#define TWO_PI 6.283185307179586f
#define RPAD 17         // padded stride for vote-stat reduction (odd -> conflict-free)

// ---- scratch (device globals; no runtime allocation) ----
__device__ float g_V[B_ * O_ * I_ * D_];          // 302 MB vote buffer, layout (b,o,i,e)
__device__ float g_ai[B_ * I_];
__device__ float g_rsum0[B_];
__device__ float g_PA1[O_ * NCHV * B_ * D_];      // iter-0 partial  sum w*V
__device__ float g_PA2[O_ * NCHV * B_ * D_];      // iter-0 partial  sum w*V^2
__device__ float g_mean[B_ * O_ * D_];
__device__ float g_i2v[B_ * O_ * D_];             // 1/(2*var+EPS)
__device__ float g_coef[B_ * O_];                 // a_j/(p1+EPS)
__device__ float g_P1[NSPLIT * B_ * O_ * D_];     // iter-1 partial sum w*V
__device__ float g_P2[NSPLIT * B_ * O_ * D_];     // iter-1 partial sum w*V^2
__device__ float g_Pr[NSPLIT * B_ * O_];          // iter-1 partial sum w

// ---------------------------------------------------------------------------
// a_i[b,i] = ||u[b,i,:]+EPS||  and  rsum0[b] = (1/O) * sum_i a_i
// ---------------------------------------------------------------------------
__global__ void k_ai(const float* __restrict__ u) {
    int b = blockIdx.x;
    int t = threadIdx.x;
    __shared__ float red[256];
    float local = 0.f;
    for (int i = t; i < I_; i += 256) {
        const float4* up = (const float4*)(u + (size_t)(b * I_ + i) * D_);
        float4 a0 = up[0], a1 = up[1], a2 = up[2], a3 = up[3];
        float s = 0.f;
        s += (a0.x+EPS)*(a0.x+EPS) + (a0.y+EPS)*(a0.y+EPS) + (a0.z+EPS)*(a0.z+EPS) + (a0.w+EPS)*(a0.w+EPS);
        s += (a1.x+EPS)*(a1.x+EPS) + (a1.y+EPS)*(a1.y+EPS) + (a1.z+EPS)*(a1.z+EPS) + (a1.w+EPS)*(a1.w+EPS);
        s += (a2.x+EPS)*(a2.x+EPS) + (a2.y+EPS)*(a2.y+EPS) + (a2.z+EPS)*(a2.z+EPS) + (a2.w+EPS)*(a2.w+EPS);
        s += (a3.x+EPS)*(a3.x+EPS) + (a3.y+EPS)*(a3.y+EPS) + (a3.z+EPS)*(a3.z+EPS) + (a3.w+EPS)*(a3.w+EPS);
        float av = sqrtf(s);
        g_ai[b * I_ + i] = av;
        local += av;
    }
    red[t] = local;
    __syncthreads();
    for (int st = 128; st > 0; st >>= 1) {
        if (t < st) red[t] += red[t + st];
        __syncthreads();
    }
    if (t == 0) g_rsum0[b] = red[0] * (1.f / O_);
}

// ---------------------------------------------------------------------------
// Votes V[b,o,i,e] = u[b,i,:]·W[o,i,e,:] + EPS + bias[o,e], fused with iter-0
// m-step moments (uniform rr -> w = a_i/64).
// Grid (o, chunk); W[o, chunk] staged in SMEM once (coalesced; each W element
// read from HBM exactly once).  Thread: b = t&63, isub = t>>6 owns 4 i's.
// Inner loop per (b,i,e): 4 broadcast LDS.128 + 16 FFMA -> FFMA-pipe bound.
// Stats reduced across isub via padded SMEM (deterministic order).
// ---------------------------------------------------------------------------
__global__ void __launch_bounds__(256) k_votes(const float* __restrict__ u,
                                               const float* __restrict__ W,
                                               const float* __restrict__ bias) {
    __shared__ float w_s[IC * 256];              // 16 KB
    __shared__ float red_s[2 * 4 * 64 * RPAD];   // ~34.8 KB
    int o  = blockIdx.x;
    int ch = blockIdx.y;
    int t  = threadIdx.x;
    int b  = t & 63;
    int isub = t >> 6;
    int i0 = ch * IC;

    // Stage W chunk (4096 floats, fully coalesced)
    const float4* Wg = (const float4*)(W + ((size_t)o * I_ + i0) * 256);
    float4* ws4 = (float4*)w_s;
#pragma unroll
    for (int k = 0; k < 4; ++k) ws4[t + 256 * k] = Wg[t + 256 * k];

    float4 bi0 = *(const float4*)(bias + o * D_ + 0);
    float4 bi1 = *(const float4*)(bias + o * D_ + 4);
    float4 bi2 = *(const float4*)(bias + o * D_ + 8);
    float4 bi3 = *(const float4*)(bias + o * D_ + 12);
    float bv[16] = {bi0.x,bi0.y,bi0.z,bi0.w, bi1.x,bi1.y,bi1.z,bi1.w,
                    bi2.x,bi2.y,bi2.z,bi2.w, bi3.x,bi3.y,bi3.z,bi3.w};
    __syncthreads();

    float s1[16], s2[16];
#pragma unroll
    for (int e = 0; e < 16; ++e) { s1[e] = 0.f; s2[e] = 0.f; }

    for (int k = 0; k < IC / 4; ++k) {
        int il = isub * (IC / 4) + k;
        int i  = i0 + il;
        const float4* up = (const float4*)(u + ((size_t)b * I_ + i) * D_);
        float4 u0 = up[0], u1 = up[1], u2 = up[2], u3 = up[3];
        float aw = g_ai[b * I_ + i] * (1.f / O_);
        const float4* wr = (const float4*)(w_s + il * 256);
        float v[16];
#pragma unroll
        for (int e = 0; e < 16; ++e) {
            float4 w0 = wr[e*4+0], w1 = wr[e*4+1], w2 = wr[e*4+2], w3 = wr[e*4+3];
            float d0 = u0.x*w0.x + u0.y*w0.y + u0.z*w0.z + u0.w*w0.w;
            float d1 = u1.x*w1.x + u1.y*w1.y + u1.z*w1.z + u1.w*w1.w;
            float d2 = u2.x*w2.x + u2.y*w2.y + u2.z*w2.z + u2.w*w2.w;
            float d3 = u3.x*w3.x + u3.y*w3.y + u3.z*w3.z + u3.w*w3.w;
            v[e] = (d0 + d1) + (d2 + d3) + EPS + bv[e];
        }
        float4* vout = (float4*)(g_V + ((size_t)(b * O_ + o) * I_ + i) * D_);
        vout[0] = make_float4(v[0], v[1], v[2], v[3]);
        vout[1] = make_float4(v[4], v[5], v[6], v[7]);
        vout[2] = make_float4(v[8], v[9], v[10], v[11]);
        vout[3] = make_float4(v[12], v[13], v[14], v[15]);
#pragma unroll
        for (int e = 0; e < 16; ++e) {
            s1[e] += aw * v[e];
            s2[e] += aw * v[e] * v[e];
        }
    }

    // Reduce isub partials (fixed order -> deterministic)
#pragma unroll
    for (int e = 0; e < 16; ++e) {
        red_s[((0 * 4 + isub) * 64 + b) * RPAD + e] = s1[e];
        red_s[((1 * 4 + isub) * 64 + b) * RPAD + e] = s2[e];
    }
    __syncthreads();
    if (isub == 0) {
#pragma unroll
        for (int e = 0; e < 16; ++e) {
            float a = 0.f, c = 0.f;
#pragma unroll
            for (int j = 0; j < 4; ++j) {
                a += red_s[((0 * 4 + j) * 64 + b) * RPAD + e];
                c += red_s[((1 * 4 + j) * 64 + b) * RPAD + e];
            }
            s1[e] = a; s2[e] = c;
        }
        float* p1 = g_PA1 + ((size_t)(o * NCHV + ch) * 64 + b) * D_;
        float* p2 = g_PA2 + ((size_t)(o * NCHV + ch) * 64 + b) * D_;
        ((float4*)p1)[0] = make_float4(s1[0], s1[1], s1[2], s1[3]);
        ((float4*)p1)[1] = make_float4(s1[4], s1[5], s1[6], s1[7]);
        ((float4*)p1)[2] = make_float4(s1[8], s1[9], s1[10], s1[11]);
        ((float4*)p1)[3] = make_float4(s1[12], s1[13], s1[14], s1[15]);
        ((float4*)p2)[0] = make_float4(s2[0], s2[1], s2[2], s2[3]);
        ((float4*)p2)[1] = make_float4(s2[4], s2[5], s2[6], s2[7]);
        ((float4*)p2)[2] = make_float4(s2[8], s2[9], s2[10], s2[11]);
        ((float4*)p2)[3] = make_float4(s2[12], s2[13], s2[14], s2[15]);
    }
}

// ---------------------------------------------------------------------------
// Iter-0 m-step finalize: combine 72 chunk partials -> mean, 1/(2var+EPS),
// coef = a_j/(p1+EPS).  One 16-lane group per (b,o), lane = e.
// ---------------------------------------------------------------------------
__global__ void k_mstep0(const float* __restrict__ beta_a,
                         const float* __restrict__ beta_u) {
    int gp = blockIdx.x * blockDim.x + threadIdx.x;
    int pair = gp >> 4;
    if (pair >= B_ * O_) return;
    int e = gp & 15;
    int b = pair >> 6;
    int o = pair & 63;
    float S = g_rsum0[b];
    float d = S + EPS;
    float s1 = 0.f, s2 = 0.f;
#pragma unroll 8
    for (int ch = 0; ch < NCHV; ++ch) {
        size_t p = ((size_t)(o * NCHV + ch) * 64 + b) * D_ + e;
        s1 += g_PA1[p];
        s2 += g_PA2[p];
    }
    float mm  = s1 / d;
    float var = (s2 - 2.f * mm * s1 + mm * mm * S) / d + 1e-4f;
    g_mean[pair * D_ + e] = mm;
    g_i2v[pair * D_ + e]  = 1.f / (2.f * var + EPS);
    float lsum = logf(var);
    float pr   = var;
#pragma unroll
    for (int off = 8; off > 0; off >>= 1) {
        lsum += __shfl_xor_sync(0xffffffffu, lsum, off, 16);
        pr   *= __shfl_xor_sync(0xffffffffu, pr,   off, 16);
    }
    if (e == 0) {
        float cost = S * (16.f * beta_u[o] + lsum);
        float aj = 1.f / (1.f + __expf(-(INVT0 * (beta_a[o] - cost))));
        float p1 = sqrtf(TWO_PI * pr + EPS);
        g_coef[pair] = aj / (p1 + EPS);
    }
}

// ---------------------------------------------------------------------------
// Fused e-step + iter-1 m-step moments.  Block = (split, b); 256 threads.
// NSPLIT=24 -> 1536 blocks, 3 resident/SM (was 1) — occupancy fix.
// ---------------------------------------------------------------------------
__global__ void __launch_bounds__(256) k_estep() {
    int s = blockIdx.x;
    int b = blockIdx.y;
    int t = threadIdx.x;
    __shared__ float sM[O_ * D_];
    __shared__ float sIV[O_ * D_];
    __shared__ float sCoef[O_];
    __shared__ float plbuf[TI][O_][5];    // pad 5 -> conflict-free
    __shared__ float apS[TI][O_ + 1];
    for (int k = t; k < O_ * D_; k += 256) {
        sM[k]  = g_mean[b * O_ * D_ + k];
        sIV[k] = g_i2v[b * O_ * D_ + k];
    }
    if (t < O_) sCoef[t] = g_coef[b * O_ + t];
    __syncthreads();
    int o  = t & 63;
    int eg = t >> 6;
    int w  = t >> 5;
    int lane = t & 31;
    float m0 = sM[o*D_ + eg*4 + 0], m1 = sM[o*D_ + eg*4 + 1];
    float m2 = sM[o*D_ + eg*4 + 2], m3 = sM[o*D_ + eg*4 + 3];
    float iv0 = sIV[o*D_ + eg*4 + 0], iv1 = sIV[o*D_ + eg*4 + 1];
    float iv2 = sIV[o*D_ + eg*4 + 2], iv3 = sIV[o*D_ + eg*4 + 3];
    float cf = sCoef[o];
    float a10 = 0.f, a11 = 0.f, a12 = 0.f, a13 = 0.f;
    float a20 = 0.f, a21 = 0.f, a22 = 0.f, a23 = 0.f;
    float rsum = 0.f;
    const float* Vb = g_V + (size_t)(b * O_ + o) * I_ * D_ + eg * 4;
    for (int tile = 0; tile < NTILE; ++tile) {
        int i0 = s * ISPLIT + tile * TI;
        float4 vv[TI];
#pragma unroll
        for (int ti = 0; ti < TI; ++ti) {
            vv[ti] = *(const float4*)(Vb + (size_t)(i0 + ti) * D_);
            float d0 = vv[ti].x - m0, d1 = vv[ti].y - m1;
            float d2 = vv[ti].z - m2, d3 = vv[ti].w - m3;
            plbuf[ti][o][eg] = d0*d0*iv0 + d1*d1*iv1 + d2*d2*iv2 + d3*d3*iv3;
        }
        __syncthreads();
#pragma unroll
        for (int q = 0; q < 2; ++q) {
            int ti = eg * 2 + q;
            float la = plbuf[ti][o][0] + plbuf[ti][o][1] + plbuf[ti][o][2] + plbuf[ti][o][3];
            apS[ti][o] = cf * __expf(-la);
        }
        __syncthreads();
        {
            float x = apS[w][lane] + apS[w][lane + 32];
#pragma unroll
            for (int off = 16; off > 0; off >>= 1)
                x += __shfl_xor_sync(0xffffffffu, x, off);
            float aiv = g_ai[b * I_ + i0 + w];
            float sc = aiv / (x + EPS);        // rr*a_i
            apS[w][lane]      *= sc;
            apS[w][lane + 32] *= sc;
        }
        __syncthreads();
#pragma unroll
        for (int ti = 0; ti < TI; ++ti) {
            float wv = apS[ti][o];
            a10 += wv * vv[ti].x; a11 += wv * vv[ti].y;
            a12 += wv * vv[ti].z; a13 += wv * vv[ti].w;
            a20 += wv * vv[ti].x * vv[ti].x; a21 += wv * vv[ti].y * vv[ti].y;
            a22 += wv * vv[ti].z * vv[ti].z; a23 += wv * vv[ti].w * vv[ti].w;
            if (eg == 0) rsum += wv;
        }
        __syncthreads();
    }
    int p = ((s * B_ + b) * O_ + o) * D_ + eg * 4;
    *(float4*)(g_P1 + p) = make_float4(a10, a11, a12, a13);
    *(float4*)(g_P2 + p) = make_float4(a20, a21, a22, a23);
    if (eg == 0) g_Pr[(s * B_ + b) * O_ + o] = rsum;
}

// ---------------------------------------------------------------------------
// Iter-1 m-step finalize + output (combine NSPLIT partials in fixed order).
// ---------------------------------------------------------------------------
__global__ void k_final(const float* __restrict__ beta_a,
                        const float* __restrict__ beta_u,
                        float* __restrict__ out) {
    int gp = blockIdx.x * blockDim.x + threadIdx.x;
    int pair = gp >> 4;
    if (pair >= B_ * O_) return;
    int e = gp & 15;
    int o = pair & 63;
    float S = 0.f, s1 = 0.f, s2 = 0.f;
#pragma unroll
    for (int s = 0; s < NSPLIT; ++s) {
        S  += g_Pr[s * B_ * O_ + pair];
        s1 += g_P1[(size_t)(s * B_ * O_ + pair) * D_ + e];
        s2 += g_P2[(size_t)(s * B_ * O_ + pair) * D_ + e];
    }
    float d = S + EPS;
    float mm  = s1 / d;
    float var = (s2 - 2.f * mm * s1 + mm * mm * S) / d + 1e-4f;
    float lsum = logf(var);
    float me = mm + EPS;
    float nr = me * me;
#pragma unroll
    for (int off = 8; off > 0; off >>= 1) {
        lsum += __shfl_xor_sync(0xffffffffu, lsum, off, 16);
        nr   += __shfl_xor_sync(0xffffffffu, nr,   off, 16);
    }
    float cost = S * (16.f * beta_u[o] + lsum);
    float aj = 1.f / (1.f + __expf(-(INVT1 * (beta_a[o] - cost))));
    out[pair * D_ + e] = aj * mm / (sqrtf(nr) + EPS);
}

extern "C" void kernel_launch(void* const* d_in, const int* in_sizes, int n_in,
                              void* d_out, int out_size) {
    const float* u      = (const float*)d_in[0];
    const float* W      = (const float*)d_in[1];
    const float* beta_a = (const float*)d_in[2];
    const float* beta_u = (const float*)d_in[3];
    const float* bias   = (const float*)d_in[4];
    float* out = (float*)d_out;

    k_ai<<<B_, 256>>>(u);
    k_votes<<<dim3(O_, NCHV), 256>>>(u, W, bias);
    k_mstep0<<<(B_ * O_ * 16 + 255) / 256, 256>>>(beta_a, beta_u);
    k_estep<<<dim3(NSPLIT, B_), 256>>>();
    k_final<<<(B_ * O_ * 16 + 255) / 256, 256>>>(beta_a, beta_u, out);
}

// round 10
// speedup vs baseline: 2.6157x; 1.4285x over previous
#include <cuda_runtime.h>

#define EPS 1e-8f
#define B_ 64
#define O_ 64
#define I_ 1152
#define D_ 16
#define IC 16           // i-chunk per vote block
#define NCHV 72         // 1152/16 chunks
#define NSPLIT 24       // i-splits in e-step kernel (1152 = 24*48)
#define ISPLIT 48
#define TI 8            // i-tile inside e-step kernel
#define NTILE 6         // 48 / 8
#define INVT0 5.0e-4f          // 0.01*(1-0.95)
#define INVT1 9.75e-4f         // 0.01*(1-0.95^2)
#define TWO_PI 6.283185307179586f

// ---- scratch (device globals; no runtime allocation) ----
__device__ float g_V[B_ * O_ * I_ * D_];          // 302 MB vote buffer, layout (b,o,i,e)
__device__ float g_u2[I_ * D_ * B_];              // u transposed: [i][d][b] (coalesced votes reads)
__device__ float g_ai[B_ * I_];
__device__ float g_aiT[I_ * B_];                  // a_i transposed: [i][b]
__device__ float g_rsum0[B_];
__device__ float g_PA1[O_ * NCHV * B_ * D_];      // iter-0 partial  sum w*V
__device__ float g_PA2[O_ * NCHV * B_ * D_];      // iter-0 partial  sum w*V^2
__device__ float g_mean[B_ * O_ * D_];
__device__ float g_i2v[B_ * O_ * D_];             // 1/(2*var+EPS)
__device__ float g_coef[B_ * O_];                 // a_j/(p1+EPS)
__device__ float g_P1[NSPLIT * B_ * O_ * D_];     // iter-1 partial sum w*V
__device__ float g_P2[NSPLIT * B_ * O_ * D_];     // iter-1 partial sum w*V^2
__device__ float g_Pr[NSPLIT * B_ * O_];          // iter-1 partial sum w

// ---------------------------------------------------------------------------
// a_i[b,i] = ||u[b,i,:]+EPS||, rsum0[b] = (1/O)*sum_i a_i, plus transposes:
// g_u2[i][d][b] and g_aiT[i][b] so k_votes reads are lane-coalesced.
// ---------------------------------------------------------------------------
__global__ void k_ai(const float* __restrict__ u) {
    int b = blockIdx.x;
    int t = threadIdx.x;
    __shared__ float red[256];
    float local = 0.f;
    for (int i = t; i < I_; i += 256) {
        const float4* up = (const float4*)(u + (size_t)(b * I_ + i) * D_);
        float4 a0 = up[0], a1 = up[1], a2 = up[2], a3 = up[3];
        float s = 0.f;
        s += (a0.x+EPS)*(a0.x+EPS) + (a0.y+EPS)*(a0.y+EPS) + (a0.z+EPS)*(a0.z+EPS) + (a0.w+EPS)*(a0.w+EPS);
        s += (a1.x+EPS)*(a1.x+EPS) + (a1.y+EPS)*(a1.y+EPS) + (a1.z+EPS)*(a1.z+EPS) + (a1.w+EPS)*(a1.w+EPS);
        s += (a2.x+EPS)*(a2.x+EPS) + (a2.y+EPS)*(a2.y+EPS) + (a2.z+EPS)*(a2.z+EPS) + (a2.w+EPS)*(a2.w+EPS);
        s += (a3.x+EPS)*(a3.x+EPS) + (a3.y+EPS)*(a3.y+EPS) + (a3.z+EPS)*(a3.z+EPS) + (a3.w+EPS)*(a3.w+EPS);
        float av = sqrtf(s);
        g_ai[b * I_ + i] = av;
        g_aiT[i * B_ + b] = av;
        // transpose u into [i][d][b]
        float ud[16] = {a0.x,a0.y,a0.z,a0.w, a1.x,a1.y,a1.z,a1.w,
                        a2.x,a2.y,a2.z,a2.w, a3.x,a3.y,a3.z,a3.w};
#pragma unroll
        for (int d = 0; d < 16; ++d)
            g_u2[(i * D_ + d) * B_ + b] = ud[d];
        local += av;
    }
    red[t] = local;
    __syncthreads();
    for (int st = 128; st > 0; st >>= 1) {
        if (t < st) red[t] += red[t + st];
        __syncthreads();
    }
    if (t == 0) g_rsum0[b] = red[0] * (1.f / O_);
}

// ---------------------------------------------------------------------------
// Votes V[b,o,i,e] = u[b,i,:]·W[o,i,e,:] + EPS + bias[o,e], fused with iter-0
// m-step moments (uniform rr -> w = a_i/64).
// Grid (o, chunk).  W chunk staged in smem (read once from HBM).  Thread:
// b = t&63, isub = t>>6; per k-step the block produces i = 4k..4k+3 and
// stages V (16 KB) in padded smem, then flushes it with linear-index mapping
// -> every warp STG.128 covers 512 B contiguous (4 lines, not 32).
// u read from g_u2 as conflict-free LDG.32 (1 line per warp instruction).
// ---------------------------------------------------------------------------
__global__ void __launch_bounds__(256) k_votes(const float* __restrict__ W,
                                               const float* __restrict__ bias) {
    __shared__ float  w_s[IC * 256];   // 16 KB
    __shared__ float4 stg[64 * 17];    // 17 KB padded stage (16 data f4 + 1 pad per b)
    int o  = blockIdx.x;
    int ch = blockIdx.y;
    int t  = threadIdx.x;
    int b  = t & 63;
    int isub = t >> 6;
    int i0 = ch * IC;

    const float4* Wg = (const float4*)(W + ((size_t)o * I_ + i0) * 256);
    float4* ws4 = (float4*)w_s;
#pragma unroll
    for (int k = 0; k < 4; ++k) ws4[t + 256 * k] = Wg[t + 256 * k];

    float4 bi0 = *(const float4*)(bias + o * D_ + 0);
    float4 bi1 = *(const float4*)(bias + o * D_ + 4);
    float4 bi2 = *(const float4*)(bias + o * D_ + 8);
    float4 bi3 = *(const float4*)(bias + o * D_ + 12);
    float bv[16] = {bi0.x,bi0.y,bi0.z,bi0.w, bi1.x,bi1.y,bi1.z,bi1.w,
                    bi2.x,bi2.y,bi2.z,bi2.w, bi3.x,bi3.y,bi3.z,bi3.w};
    __syncthreads();

    float s1[16], s2[16];
#pragma unroll
    for (int e = 0; e < 16; ++e) { s1[e] = 0.f; s2[e] = 0.f; }

    for (int k = 0; k < 4; ++k) {
        int il = 4 * k + isub;               // block covers contiguous i's 4k..4k+3
        int i  = i0 + il;
        float ur[16];
#pragma unroll
        for (int d = 0; d < 16; ++d)
            ur[d] = g_u2[(i * D_ + d) * B_ + b];       // coalesced LDG.32
        float aw = g_aiT[i * B_ + b] * (1.f / O_);     // coalesced
        const float* wr = w_s + il * 256;
#pragma unroll
        for (int eg = 0; eg < 4; ++eg) {
            float v[4];
#pragma unroll
            for (int j = 0; j < 4; ++j) {
                const float* wp = wr + (eg * 4 + j) * 16;
                float d0 = ur[0]*wp[0]  + ur[1]*wp[1]  + ur[2]*wp[2]  + ur[3]*wp[3];
                float d1 = ur[4]*wp[4]  + ur[5]*wp[5]  + ur[6]*wp[6]  + ur[7]*wp[7];
                float d2 = ur[8]*wp[8]  + ur[9]*wp[9]  + ur[10]*wp[10]+ ur[11]*wp[11];
                float d3 = ur[12]*wp[12]+ ur[13]*wp[13]+ ur[14]*wp[14]+ ur[15]*wp[15];
                v[j] = (d0 + d1) + (d2 + d3) + EPS + bv[eg*4 + j];
                s1[eg*4 + j] += aw * v[j];
                s2[eg*4 + j] += aw * v[j] * v[j];
            }
            stg[b * 17 + isub * 4 + eg] = make_float4(v[0], v[1], v[2], v[3]);
        }
        __syncthreads();
        // flush 16 KB stage -> global, coalesced (warp = 32 consecutive float4)
#pragma unroll
        for (int j = 0; j < 4; ++j) {
            int idx = j * 256 + t;
            int bb = idx >> 4, r = idx & 15;
            ((float4*)g_V)[((size_t)(bb * O_ + o) * I_ + (i0 + 4*k)) * 4 + r] =
                stg[bb * 17 + r];
        }
        __syncthreads();
    }

    // deterministic isub reduction of s1 then s2 through the stage buffer
#pragma unroll
    for (int eg = 0; eg < 4; ++eg)
        stg[b * 17 + isub * 4 + eg] = make_float4(s1[eg*4], s1[eg*4+1], s1[eg*4+2], s1[eg*4+3]);
    __syncthreads();
    if (isub == 0) {
        float4* p1 = (float4*)(g_PA1 + ((size_t)(o * NCHV + ch) * B_ + b) * D_);
#pragma unroll
        for (int eg = 0; eg < 4; ++eg) {
            float4 r0 = stg[b*17 + 0 + eg], r1 = stg[b*17 + 4 + eg];
            float4 r2 = stg[b*17 + 8 + eg], r3 = stg[b*17 + 12 + eg];
            p1[eg] = make_float4(((r0.x+r1.x)+(r2.x+r3.x)), ((r0.y+r1.y)+(r2.y+r3.y)),
                                 ((r0.z+r1.z)+(r2.z+r3.z)), ((r0.w+r1.w)+(r2.w+r3.w)));
        }
    }
    __syncthreads();
#pragma unroll
    for (int eg = 0; eg < 4; ++eg)
        stg[b * 17 + isub * 4 + eg] = make_float4(s2[eg*4], s2[eg*4+1], s2[eg*4+2], s2[eg*4+3]);
    __syncthreads();
    if (isub == 0) {
        float4* p2 = (float4*)(g_PA2 + ((size_t)(o * NCHV + ch) * B_ + b) * D_);
#pragma unroll
        for (int eg = 0; eg < 4; ++eg) {
            float4 r0 = stg[b*17 + 0 + eg], r1 = stg[b*17 + 4 + eg];
            float4 r2 = stg[b*17 + 8 + eg], r3 = stg[b*17 + 12 + eg];
            p2[eg] = make_float4(((r0.x+r1.x)+(r2.x+r3.x)), ((r0.y+r1.y)+(r2.y+r3.y)),
                                 ((r0.z+r1.z)+(r2.z+r3.z)), ((r0.w+r1.w)+(r2.w+r3.w)));
        }
    }
}

// ---------------------------------------------------------------------------
// Iter-0 m-step finalize: combine 72 chunk partials -> mean, 1/(2var+EPS),
// coef = a_j/(p1+EPS).  One 16-lane group per (b,o), lane = e.
// ---------------------------------------------------------------------------
__global__ void k_mstep0(const float* __restrict__ beta_a,
                         const float* __restrict__ beta_u) {
    int gp = blockIdx.x * blockDim.x + threadIdx.x;
    int pair = gp >> 4;
    if (pair >= B_ * O_) return;
    int e = gp & 15;
    int b = pair >> 6;
    int o = pair & 63;
    float S = g_rsum0[b];
    float d = S + EPS;
    float s1 = 0.f, s2 = 0.f;
#pragma unroll 8
    for (int ch = 0; ch < NCHV; ++ch) {
        size_t p = ((size_t)(o * NCHV + ch) * B_ + b) * D_ + e;
        s1 += g_PA1[p];
        s2 += g_PA2[p];
    }
    float mm  = s1 / d;
    float var = (s2 - 2.f * mm * s1 + mm * mm * S) / d + 1e-4f;
    g_mean[pair * D_ + e] = mm;
    g_i2v[pair * D_ + e]  = 1.f / (2.f * var + EPS);
    float lsum = logf(var);
    float pr   = var;
#pragma unroll
    for (int off = 8; off > 0; off >>= 1) {
        lsum += __shfl_xor_sync(0xffffffffu, lsum, off, 16);
        pr   *= __shfl_xor_sync(0xffffffffu, pr,   off, 16);
    }
    if (e == 0) {
        float cost = S * (16.f * beta_u[o] + lsum);
        float aj = 1.f / (1.f + __expf(-(INVT0 * (beta_a[o] - cost))));
        float p1 = sqrtf(TWO_PI * pr + EPS);
        g_coef[pair] = aj / (p1 + EPS);
    }
}

// ---------------------------------------------------------------------------
// Fused e-step + iter-1 m-step moments.  Block = (split, b), 256 threads.
// V tile (64 o x 8 i x 16 e = 32 KB) loaded COOPERATIVELY into smem with
// linear-index mapping: every warp LDG.128 covers 512 B contiguous of one
// o-row (4 lines/instr, was 32).  Compute phases read smem twice.
// Per-thread m[16]/iv[16] in registers (thread owns one o).
// ---------------------------------------------------------------------------
__global__ void __launch_bounds__(256) k_estep() {
    int s = blockIdx.x;
    int b = blockIdx.y;
    int t = threadIdx.x;
    int o  = t & 63;
    int eg = t >> 6;          // also ti-pair selector in phase 2
    int w  = t >> 5;
    int lane = t & 31;
    __shared__ float4 sV[64 * 33];        // 33 f4 per o-row (32 data + 1 pad) = 33.8 KB
    __shared__ float  apS[TI][O_ + 1];

    float m[16], iv[16];
    {
        const float4* mp = (const float4*)(g_mean + ((size_t)b * O_ + o) * D_);
        const float4* ip = (const float4*)(g_i2v  + ((size_t)b * O_ + o) * D_);
#pragma unroll
        for (int j = 0; j < 4; ++j) {
            float4 a = mp[j];
            m[j*4+0]=a.x; m[j*4+1]=a.y; m[j*4+2]=a.z; m[j*4+3]=a.w;
            float4 c = ip[j];
            iv[j*4+0]=c.x; iv[j*4+1]=c.y; iv[j*4+2]=c.z; iv[j*4+3]=c.w;
        }
    }
    float cf = g_coef[b * O_ + o];
    float a10=0.f,a11=0.f,a12=0.f,a13=0.f;
    float a20=0.f,a21=0.f,a22=0.f,a23=0.f;
    float rsum = 0.f;
    const float4* Vg = (const float4*)g_V;

    for (int tile = 0; tile < NTILE; ++tile) {
        int i0 = s * ISPLIT + tile * TI;
        // phase 1: cooperative coalesced tile load
#pragma unroll
        for (int j = 0; j < 8; ++j) {
            int idx = j * 256 + t;
            int oo = idx >> 5, r = idx & 31;
            sV[oo * 33 + r] = Vg[((size_t)(b * O_ + oo) * I_ + i0) * 4 + r];
        }
        __syncthreads();
        // phase 2: full Mahalanobis + exp; thread handles ti = 2*eg, 2*eg+1
#pragma unroll
        for (int p = 0; p < 2; ++p) {
            int ti = eg * 2 + p;
            const float4* vp = &sV[o * 33 + ti * 4];
            float la = 0.f;
#pragma unroll
            for (int j = 0; j < 4; ++j) {
                float4 x = vp[j];
                float d0 = x.x - m[j*4+0], d1 = x.y - m[j*4+1];
                float d2 = x.z - m[j*4+2], d3 = x.w - m[j*4+3];
                la += d0*d0*iv[j*4+0] + d1*d1*iv[j*4+1] + d2*d2*iv[j*4+2] + d3*d3*iv[j*4+3];
            }
            apS[ti][o] = cf * __expf(-la);
        }
        __syncthreads();
        // phase 3: softmax-denominator across o for row ti = w, apply a_i
        {
            float x = apS[w][lane] + apS[w][lane + 32];
#pragma unroll
            for (int off = 16; off > 0; off >>= 1)
                x += __shfl_xor_sync(0xffffffffu, x, off);
            float aiv = g_ai[b * I_ + i0 + w];
            float sc = aiv / (x + EPS);        // rr * a_i
            apS[w][lane]      *= sc;
            apS[w][lane + 32] *= sc;
        }
        __syncthreads();
        // phase 4: accumulate weighted moments; thread owns (o, eg)
#pragma unroll
        for (int ti = 0; ti < TI; ++ti) {
            float wv = apS[ti][o];
            float4 x = sV[o * 33 + ti * 4 + eg];
            a10 += wv * x.x; a11 += wv * x.y; a12 += wv * x.z; a13 += wv * x.w;
            a20 += wv * x.x * x.x; a21 += wv * x.y * x.y;
            a22 += wv * x.z * x.z; a23 += wv * x.w * x.w;
            if (eg == 0) rsum += wv;
        }
        __syncthreads();
    }
    int p = ((s * B_ + b) * O_ + o) * D_ + eg * 4;
    *(float4*)(g_P1 + p) = make_float4(a10, a11, a12, a13);
    *(float4*)(g_P2 + p) = make_float4(a20, a21, a22, a23);
    if (eg == 0) g_Pr[(s * B_ + b) * O_ + o] = rsum;
}

// ---------------------------------------------------------------------------
// Iter-1 m-step finalize + output (combine NSPLIT partials in fixed order).
// ---------------------------------------------------------------------------
__global__ void k_final(const float* __restrict__ beta_a,
                        const float* __restrict__ beta_u,
                        float* __restrict__ out) {
    int gp = blockIdx.x * blockDim.x + threadIdx.x;
    int pair = gp >> 4;
    if (pair >= B_ * O_) return;
    int e = gp & 15;
    int o = pair & 63;
    float S = 0.f, s1 = 0.f, s2 = 0.f;
#pragma unroll
    for (int s = 0; s < NSPLIT; ++s) {
        S  += g_Pr[s * B_ * O_ + pair];
        s1 += g_P1[(size_t)(s * B_ * O_ + pair) * D_ + e];
        s2 += g_P2[(size_t)(s * B_ * O_ + pair) * D_ + e];
    }
    float d = S + EPS;
    float mm  = s1 / d;
    float var = (s2 - 2.f * mm * s1 + mm * mm * S) / d + 1e-4f;
    float lsum = logf(var);
    float me = mm + EPS;
    float nr = me * me;
#pragma unroll
    for (int off = 8; off > 0; off >>= 1) {
        lsum += __shfl_xor_sync(0xffffffffu, lsum, off, 16);
        nr   += __shfl_xor_sync(0xffffffffu, nr,   off, 16);
    }
    float cost = S * (16.f * beta_u[o] + lsum);
    float aj = 1.f / (1.f + __expf(-(INVT1 * (beta_a[o] - cost))));
    out[pair * D_ + e] = aj * mm / (sqrtf(nr) + EPS);
}

extern "C" void kernel_launch(void* const* d_in, const int* in_sizes, int n_in,
                              void* d_out, int out_size) {
    const float* u      = (const float*)d_in[0];
    const float* W      = (const float*)d_in[1];
    const float* beta_a = (const float*)d_in[2];
    const float* beta_u = (const float*)d_in[3];
    const float* bias   = (const float*)d_in[4];
    float* out = (float*)d_out;

    k_ai<<<B_, 256>>>(u);
    k_votes<<<dim3(O_, NCHV), 256>>>(W, bias);
    k_mstep0<<<(B_ * O_ * 16 + 255) / 256, 256>>>(beta_a, beta_u);
    k_estep<<<dim3(NSPLIT, B_), 256>>>();
    k_final<<<(B_ * O_ * 16 + 255) / 256, 256>>>(beta_a, beta_u, out);
}